// round 4
// baseline (speedup 1.0000x reference)
#include <cuda_runtime.h>
#include <cuda_bf16.h>
#include <cstdint>

#define SEQ 4096
#define DM  1024
#define NH  16
#define HD  64

// ---------------------------------------------------------------------------
// Scratch (__device__ globals; allocation in kernel_launch is forbidden)
// ---------------------------------------------------------------------------
static __device__ float g_Q [SEQ * DM];
static __device__ float g_K [SEQ * DM];
static __device__ float g_V [SEQ * DM];
static __device__ float g_AO[SEQ * DM];

// bf16 hi/lo planes, reused sequentially across the four GEMMs
static __device__ __nv_bfloat16 g_ahi[SEQ * DM];
static __device__ __nv_bfloat16 g_alo[SEQ * DM];
static __device__ __nv_bfloat16 g_whi[DM * DM];
static __device__ __nv_bfloat16 g_wlo[DM * DM];

// ---------------------------------------------------------------------------
// fp32 -> (bf16 hi, bf16 lo) split: x ≈ hi + lo, residual ~2^-17 * |x|
// ---------------------------------------------------------------------------
__global__ void __launch_bounds__(256)
split_bf16(const float* __restrict__ x,
           __nv_bfloat16* __restrict__ hi, __nv_bfloat16* __restrict__ lo, int n)
{
    int i = (blockIdx.x * 256 + threadIdx.x) * 4;
    if (i >= n) return;
    float4 v = *(const float4*)(x + i);
    float vv[4] = {v.x, v.y, v.z, v.w};
    __nv_bfloat16 h[4], l[4];
#pragma unroll
    for (int j = 0; j < 4; j++) {
        h[j] = __float2bfloat16(vv[j]);
        l[j] = __float2bfloat16(vv[j] - __bfloat162float(h[j]));
    }
    *(__nv_bfloat162*)(hi + i)     = __nv_bfloat162(h[0], h[1]);
    *(__nv_bfloat162*)(hi + i + 2) = __nv_bfloat162(h[2], h[3]);
    *(__nv_bfloat162*)(lo + i)     = __nv_bfloat162(l[0], l[1]);
    *(__nv_bfloat162*)(lo + i + 2) = __nv_bfloat162(l[2], l[3]);
}

// ---------------------------------------------------------------------------
// Tensor-core GEMM: C[M,N] = A[M,K] @ W[N,K]^T + bias[N]
// A,W given as bf16 hi/lo planes. 128x128 CTA tile, BK=64, 8 warps (2m x 4n),
// warp tile 64x32, mma.sync.m16n8k16, 3-way split (hh + hl + lh).
// ---------------------------------------------------------------------------
#define GP 72   // smem pitch in bf16 elems (144B): 4-bank shift/row, conflict-free
#define GEMM_SMEM (4 * 128 * GP * 2)   // 4 planes * 128 rows * 72 bf16 * 2B

__device__ __forceinline__ uint32_t lds32(const __nv_bfloat16* p) {
    return *(const uint32_t*)p;
}

__device__ __forceinline__ void mma16816(float* c, const uint32_t* a, const uint32_t* b) {
    asm volatile(
        "mma.sync.aligned.m16n8k16.row.col.f32.bf16.bf16.f32 "
        "{%0,%1,%2,%3}, {%4,%5,%6,%7}, {%8,%9}, {%0,%1,%2,%3};\n"
        : "+f"(c[0]), "+f"(c[1]), "+f"(c[2]), "+f"(c[3])
        : "r"(a[0]), "r"(a[1]), "r"(a[2]), "r"(a[3]), "r"(b[0]), "r"(b[1]));
}

__global__ void __launch_bounds__(256, 1)
gemm_bf16s(const __nv_bfloat16* __restrict__ Ahi, const __nv_bfloat16* __restrict__ Alo,
           const __nv_bfloat16* __restrict__ Whi, const __nv_bfloat16* __restrict__ Wlo,
           const float* __restrict__ bias, float* __restrict__ C,
           int M, int N, int K)
{
    extern __shared__ __nv_bfloat16 sm[];
    __nv_bfloat16* sAh = sm;
    __nv_bfloat16* sAl = sAh + 128 * GP;
    __nv_bfloat16* sBh = sAl + 128 * GP;
    __nv_bfloat16* sBl = sBh + 128 * GP;

    const int tid  = threadIdx.x;
    const int lane = tid & 31;
    const int wid  = tid >> 5;
    const int wm   = (wid >> 2) * 64;      // warp m offset: 0 / 64
    const int wn   = (wid & 3) * 32;       // warp n offset: 0..96
    const int lr   = lane >> 2;            // 0..7
    const int lc   = (lane & 3) * 2;       // 0,2,4,6

    const int bm0 = blockIdx.y * 128;
    const int bn0 = blockIdx.x * 128;

    const __nv_bfloat16* Abh = Ahi + (size_t)bm0 * K;
    const __nv_bfloat16* Abl = Alo + (size_t)bm0 * K;
    const __nv_bfloat16* Wbh = Whi + (size_t)bn0 * K;
    const __nv_bfloat16* Wbl = Wlo + (size_t)bn0 * K;

    float acc[4][4][4];
#pragma unroll
    for (int i = 0; i < 4; i++)
#pragma unroll
        for (int j = 0; j < 4; j++)
#pragma unroll
            for (int r = 0; r < 4; r++) acc[i][j][r] = 0.f;

    const int NK = K >> 6;   // BK = 64
    for (int kt = 0; kt < NK; kt++) {
        __syncthreads();
#pragma unroll
        for (int i = 0; i < 4; i++) {
            int ch  = tid + 256 * i;
            int row = ch >> 3;
            int kc8 = (ch & 7) * 8;
            size_t go = (size_t)row * K + kt * 64 + kc8;
            int    so = row * GP + kc8;
            *(uint4*)(sAh + so) = *(const uint4*)(Abh + go);
            *(uint4*)(sAl + so) = *(const uint4*)(Abl + go);
            *(uint4*)(sBh + so) = *(const uint4*)(Wbh + go);
            *(uint4*)(sBl + so) = *(const uint4*)(Wbl + go);
        }
        __syncthreads();

#pragma unroll
        for (int kc = 0; kc < 4; kc++) {
            const int kb = kc * 16 + lc;
            uint32_t ah[4][4], al[4][4], bh[4][2], bl[4][2];
#pragma unroll
            for (int mf = 0; mf < 4; mf++) {
                const __nv_bfloat16* p = sAh + (wm + mf * 16 + lr) * GP + kb;
                const __nv_bfloat16* q = sAl + (wm + mf * 16 + lr) * GP + kb;
                ah[mf][0] = lds32(p);            ah[mf][1] = lds32(p + 8 * GP);
                ah[mf][2] = lds32(p + 8);        ah[mf][3] = lds32(p + 8 * GP + 8);
                al[mf][0] = lds32(q);            al[mf][1] = lds32(q + 8 * GP);
                al[mf][2] = lds32(q + 8);        al[mf][3] = lds32(q + 8 * GP + 8);
            }
#pragma unroll
            for (int nf = 0; nf < 4; nf++) {
                const __nv_bfloat16* p = sBh + (wn + nf * 8 + lr) * GP + kb;
                const __nv_bfloat16* q = sBl + (wn + nf * 8 + lr) * GP + kb;
                bh[nf][0] = lds32(p);  bh[nf][1] = lds32(p + 8);
                bl[nf][0] = lds32(q);  bl[nf][1] = lds32(q + 8);
            }
            // hi*hi
#pragma unroll
            for (int mf = 0; mf < 4; mf++)
#pragma unroll
                for (int nf = 0; nf < 4; nf++)
                    mma16816(acc[mf][nf], ah[mf], bh[nf]);
            // hi*lo
#pragma unroll
            for (int mf = 0; mf < 4; mf++)
#pragma unroll
                for (int nf = 0; nf < 4; nf++)
                    mma16816(acc[mf][nf], ah[mf], bl[nf]);
            // lo*hi
#pragma unroll
            for (int mf = 0; mf < 4; mf++)
#pragma unroll
                for (int nf = 0; nf < 4; nf++)
                    mma16816(acc[mf][nf], al[mf], bh[nf]);
        }
    }

    // Epilogue
    float2 b2[4];
#pragma unroll
    for (int nf = 0; nf < 4; nf++) {
        int col = bn0 + wn + nf * 8 + lc;
        b2[nf] = make_float2(bias[col], bias[col + 1]);
    }
#pragma unroll
    for (int mf = 0; mf < 4; mf++) {
        int r = bm0 + wm + mf * 16 + lr;
#pragma unroll
        for (int nf = 0; nf < 4; nf++) {
            int c = bn0 + wn + nf * 8 + lc;
            *(float2*)&C[(size_t)r * N + c] =
                make_float2(acc[mf][nf][0] + b2[nf].x, acc[mf][nf][1] + b2[nf].y);
            *(float2*)&C[(size_t)(r + 8) * N + c] =
                make_float2(acc[mf][nf][2] + b2[nf].x, acc[mf][nf][3] + b2[nf].y);
        }
    }
}

// ---------------------------------------------------------------------------
// Causal flash attention, fp32 (unchanged from round 1; next optimization target).
// ---------------------------------------------------------------------------
#define QP 68
#define FLASH_SMEM ((64 * QP * 3 + 64 * 64 + 3 * 64) * 4)

__global__ void __launch_bounds__(256)
flash_attn()
{
    extern __shared__ float smf[];
    float* Qs  = smf;
    float* Ks  = Qs + 64 * QP;
    float* Vs  = Ks + 64 * QP;
    float* Ss  = Vs + 64 * 64;
    float* m_s = Ss + 64 * QP;
    float* l_s = m_s + 64;
    float* a_s = l_s + 64;

    const int tid = threadIdx.x;
    const int tm  = tid >> 4;
    const int tn  = tid & 15;
    const int h   = blockIdx.y;
    const int qt  = (int)gridDim.x - 1 - (int)blockIdx.x;
    const int q0  = qt * 64;
    const size_t hoff = (size_t)h * HD;

#pragma unroll
    for (int s = 0; s < 4; s++) {
        int idx = tid + 256 * s;
        int r = idx >> 4;
        int c = (idx & 15) << 2;
        float4 q4 = *(const float4*)&g_Q[(size_t)(q0 + r) * DM + hoff + c];
        Qs[(c + 0) * QP + r] = q4.x * 0.125f;
        Qs[(c + 1) * QP + r] = q4.y * 0.125f;
        Qs[(c + 2) * QP + r] = q4.z * 0.125f;
        Qs[(c + 3) * QP + r] = q4.w * 0.125f;
    }
    if (tid < 64) { m_s[tid] = -1e30f; l_s[tid] = 0.f; }

    float o[4][4] = {};

    for (int kt = 0; kt <= qt; kt++) {
        const int k0 = kt * 64;
        __syncthreads();

#pragma unroll
        for (int s = 0; s < 4; s++) {
            int idx = tid + 256 * s;
            int r = idx >> 4;
            int c = (idx & 15) << 2;
            float4 k4 = *(const float4*)&g_K[(size_t)(k0 + r) * DM + hoff + c];
            Ks[(c + 0) * QP + r] = k4.x;
            Ks[(c + 1) * QP + r] = k4.y;
            Ks[(c + 2) * QP + r] = k4.z;
            Ks[(c + 3) * QP + r] = k4.w;
            float4 v4 = *(const float4*)&g_V[(size_t)(k0 + r) * DM + hoff + c];
            *(float4*)&Vs[r * 64 + c] = v4;
        }
        __syncthreads();

        float sacc[4][4] = {};
#pragma unroll 8
        for (int d = 0; d < 64; d++) {
            float4 qa = *(const float4*)&Qs[d * QP + (tm << 2)];
            float4 kb = *(const float4*)&Ks[d * QP + (tn << 2)];
            float aq[4] = {qa.x, qa.y, qa.z, qa.w};
            float bk[4] = {kb.x, kb.y, kb.z, kb.w};
#pragma unroll
            for (int i = 0; i < 4; i++)
#pragma unroll
                for (int j = 0; j < 4; j++)
                    sacc[i][j] = fmaf(aq[i], bk[j], sacc[i][j]);
        }

        if (kt == qt) {
#pragma unroll
            for (int i = 0; i < 4; i++)
#pragma unroll
                for (int j = 0; j < 4; j++)
                    if ((tn << 2) + j > (tm << 2) + i) sacc[i][j] = -1e30f;
        }

#pragma unroll
        for (int j = 0; j < 4; j++) {
            *(float4*)&Ss[((tn << 2) + j) * QP + (tm << 2)] =
                make_float4(sacc[0][j], sacc[1][j], sacc[2][j], sacc[3][j]);
        }
        __syncthreads();

        if (tid < 64) {
            float mi = m_s[tid];
            float mx = mi;
#pragma unroll 8
            for (int j = 0; j < 64; j++) mx = fmaxf(mx, Ss[j * QP + tid]);
            float alpha = __expf(mi - mx);
            float sum = 0.f;
#pragma unroll 8
            for (int j = 0; j < 64; j++) {
                float p = __expf(Ss[j * QP + tid] - mx);
                Ss[j * QP + tid] = p;
                sum += p;
            }
            m_s[tid] = mx;
            l_s[tid] = l_s[tid] * alpha + sum;
            a_s[tid] = alpha;
        }
        __syncthreads();

        {
            float al4[4];
#pragma unroll
            for (int i = 0; i < 4; i++) al4[i] = a_s[(tm << 2) + i];
#pragma unroll
            for (int i = 0; i < 4; i++)
#pragma unroll
                for (int j = 0; j < 4; j++) o[i][j] *= al4[i];
        }
#pragma unroll 4
        for (int j = 0; j < 64; j++) {
            float4 pa = *(const float4*)&Ss[j * QP + (tm << 2)];
            float4 vb = *(const float4*)&Vs[j * 64 + (tn << 2)];
            float pp[4] = {pa.x, pa.y, pa.z, pa.w};
            float vv[4] = {vb.x, vb.y, vb.z, vb.w};
#pragma unroll
            for (int i = 0; i < 4; i++)
#pragma unroll
                for (int v = 0; v < 4; v++)
                    o[i][v] = fmaf(pp[i], vv[v], o[i][v]);
        }
    }

#pragma unroll
    for (int i = 0; i < 4; i++) {
        float inv = 1.f / l_s[(tm << 2) + i];
        *(float4*)&g_AO[(size_t)(q0 + (tm << 2) + i) * DM + hoff + (tn << 2)] =
            make_float4(o[i][0] * inv, o[i][1] * inv, o[i][2] * inv, o[i][3] * inv);
    }
}

// ---------------------------------------------------------------------------
extern "C" void kernel_launch(void* const* d_in, const int* in_sizes, int n_in,
                              void* d_out, int out_size)
{
    const float* queries = (const float*)d_in[0];
    const float* keys    = (const float*)d_in[1];
    const float* values  = (const float*)d_in[2];
    const float* Wq      = (const float*)d_in[3];
    const float* bq      = (const float*)d_in[4];
    const float* Wk      = (const float*)d_in[5];
    const float* bk      = (const float*)d_in[6];
    const float* Wv      = (const float*)d_in[7];
    const float* bv      = (const float*)d_in[8];
    const float* Wo      = (const float*)d_in[9];
    const float* bo      = (const float*)d_in[10];
    float* out = (float*)d_out;

    float *Qp, *Kp, *Vp, *AOp;
    __nv_bfloat16 *ahi, *alo, *whi, *wlo;
    cudaGetSymbolAddress((void**)&Qp,  g_Q);
    cudaGetSymbolAddress((void**)&Kp,  g_K);
    cudaGetSymbolAddress((void**)&Vp,  g_V);
    cudaGetSymbolAddress((void**)&AOp, g_AO);
    cudaGetSymbolAddress((void**)&ahi, g_ahi);
    cudaGetSymbolAddress((void**)&alo, g_alo);
    cudaGetSymbolAddress((void**)&whi, g_whi);
    cudaGetSymbolAddress((void**)&wlo, g_wlo);

    cudaFuncSetAttribute(flash_attn, cudaFuncAttributeMaxDynamicSharedMemorySize,
                         FLASH_SMEM);
    cudaFuncSetAttribute(gemm_bf16s, cudaFuncAttributeMaxDynamicSharedMemorySize,
                         GEMM_SMEM);

    const int nA = SEQ * DM;     // 4M elems
    const int nW = DM * DM;      // 1M elems
    dim3 cgA(nA / 1024), cgW(nW / 1024);
    dim3 ggrid(DM / 128, SEQ / 128);   // (8, 32)

    // Q projection
    split_bf16<<<cgA, 256>>>(queries, ahi, alo, nA);
    split_bf16<<<cgW, 256>>>(Wq, whi, wlo, nW);
    gemm_bf16s<<<ggrid, 256, GEMM_SMEM>>>(ahi, alo, whi, wlo, bq, Qp, SEQ, DM, DM);
    // K projection
    split_bf16<<<cgA, 256>>>(keys, ahi, alo, nA);
    split_bf16<<<cgW, 256>>>(Wk, whi, wlo, nW);
    gemm_bf16s<<<ggrid, 256, GEMM_SMEM>>>(ahi, alo, whi, wlo, bk, Kp, SEQ, DM, DM);
    // V projection
    split_bf16<<<cgA, 256>>>(values, ahi, alo, nA);
    split_bf16<<<cgW, 256>>>(Wv, whi, wlo, nW);
    gemm_bf16s<<<ggrid, 256, GEMM_SMEM>>>(ahi, alo, whi, wlo, bv, Vp, SEQ, DM, DM);

    // Attention (fp32)
    flash_attn<<<dim3(SEQ / 64, NH), 256, FLASH_SMEM>>>();

    // Output projection
    split_bf16<<<cgA, 256>>>(AOp, ahi, alo, nA);
    split_bf16<<<cgW, 256>>>(Wo, whi, wlo, nW);
    gemm_bf16s<<<ggrid, 256, GEMM_SMEM>>>(ahi, alo, whi, wlo, bo, out, SEQ, DM, DM);
}

// round 10
// speedup vs baseline: 1.2885x; 1.2885x over previous
#include <cuda_runtime.h>
#include <cstdint>

#define SEQ 4096
#define DM  1024
#define NH  16
#define HD  64

// Scratch (allocation inside kernel_launch is forbidden).
static __device__ float g_Q [SEQ * DM];
static __device__ float g_K [SEQ * DM];
static __device__ float g_V [SEQ * DM];
static __device__ float g_AO[SEQ * DM];

// ---------------------------------------------------------------------------
// Packed fp32x2 helpers (Blackwell FFMA2 path; plain fp32 IEEE per lane)
// ---------------------------------------------------------------------------
typedef unsigned long long u64t;

__device__ __forceinline__ void ffma2(u64t& d, u64t a, u64t b) {
    asm("fma.rn.f32x2 %0, %1, %2, %0;" : "+l"(d) : "l"(a), "l"(b));
}
__device__ __forceinline__ void fmul2(u64t& d, u64t a, u64t b) {
    asm("mul.rn.f32x2 %0, %1, %2;" : "=l"(d) : "l"(a), "l"(b));
}
__device__ __forceinline__ u64t packdup(float x) {
    u64t r;
    asm("mov.b64 %0, {%1, %1};" : "=l"(r) : "f"(x));
    return r;
}
__device__ __forceinline__ void unpack2(float& lo, float& hi, u64t v) {
    asm("mov.b64 {%0, %1}, %2;" : "=f"(lo), "=f"(hi) : "l"(v));
}

// ---------------------------------------------------------------------------
// GEMM: C[M,N] = A[M,K] @ W[N,K]^T + bias[N]
// 128x128 block tile, K-tile 16, 256 threads, 8x8 per-thread micro-tile,
// register prefetch, inner product via fma.rn.f32x2 (row-pairs x dup-B).
// ---------------------------------------------------------------------------
__global__ void __launch_bounds__(256, 2)
gemm_bias(const float* __restrict__ A, const float* __restrict__ W,
          const float* __restrict__ bias, float* __restrict__ C,
          int M, int N, int K)
{
    __shared__ float As[16][132];   // [k][m], padded
    __shared__ float Ws[16][132];   // [k][n], padded

    const int tid = threadIdx.x;
    const int tm  = tid >> 4;       // 0..15
    const int tn  = tid & 15;       // 0..15
    const int bm  = blockIdx.y;
    const int bn  = blockIdx.x;

    const int i0  = tid * 2;
    const int ar0 = i0 >> 2,       ac0 = (i0 & 3) << 2;
    const int ar1 = (i0 + 1) >> 2, ac1 = ((i0 + 1) & 3) << 2;

    const float* Ab = A + (size_t)bm * 128 * K;
    const float* Wb = W + (size_t)bn * 128 * K;

    // acc2[ip][j] = { C[2ip][j], C[2ip+1][j] } of the 8x8 micro-tile
    u64t acc2[4][8];
    #pragma unroll
    for (int i = 0; i < 4; i++)
        #pragma unroll
        for (int j = 0; j < 8; j++) acc2[i][j] = 0ull;

    const int NK = K >> 4;

    float4 a0 = *(const float4*)(Ab + (size_t)ar0 * K + ac0);
    float4 a1 = *(const float4*)(Ab + (size_t)ar1 * K + ac1);
    float4 w0 = *(const float4*)(Wb + (size_t)ar0 * K + ac0);
    float4 w1 = *(const float4*)(Wb + (size_t)ar1 * K + ac1);
    As[ac0+0][ar0] = a0.x; As[ac0+1][ar0] = a0.y; As[ac0+2][ar0] = a0.z; As[ac0+3][ar0] = a0.w;
    As[ac1+0][ar1] = a1.x; As[ac1+1][ar1] = a1.y; As[ac1+2][ar1] = a1.z; As[ac1+3][ar1] = a1.w;
    Ws[ac0+0][ar0] = w0.x; Ws[ac0+1][ar0] = w0.y; Ws[ac0+2][ar0] = w0.z; Ws[ac0+3][ar0] = w0.w;
    Ws[ac1+0][ar1] = w1.x; Ws[ac1+1][ar1] = w1.y; Ws[ac1+2][ar1] = w1.z; Ws[ac1+3][ar1] = w1.w;
    __syncthreads();

    for (int kt = 0; kt < NK; kt++) {
        const bool more = (kt + 1 < NK);
        float4 na0, na1, nw0, nw1;
        if (more) {
            const float* Ap = Ab + (kt + 1) * 16;
            const float* Wp = Wb + (kt + 1) * 16;
            na0 = *(const float4*)(Ap + (size_t)ar0 * K + ac0);
            na1 = *(const float4*)(Ap + (size_t)ar1 * K + ac1);
            nw0 = *(const float4*)(Wp + (size_t)ar0 * K + ac0);
            nw1 = *(const float4*)(Wp + (size_t)ar1 * K + ac1);
        }

        #pragma unroll
        for (int kk = 0; kk < 16; kk++) {
            // A row-pairs: 8 contiguous floats -> 4 packed f32x2 (16B-aligned)
            ulonglong2 av0 = *(const ulonglong2*)&As[kk][tm * 8];
            ulonglong2 av1 = *(const ulonglong2*)&As[kk][tm * 8 + 4];
            u64t a2[4] = {av0.x, av0.y, av1.x, av1.y};
            // B scalars duplicated into both lanes
            float4 bv0 = *(const float4*)&Ws[kk][tn * 8];
            float4 bv1 = *(const float4*)&Ws[kk][tn * 8 + 4];
            u64t bd[8];
            bd[0] = packdup(bv0.x); bd[1] = packdup(bv0.y);
            bd[2] = packdup(bv0.z); bd[3] = packdup(bv0.w);
            bd[4] = packdup(bv1.x); bd[5] = packdup(bv1.y);
            bd[6] = packdup(bv1.z); bd[7] = packdup(bv1.w);
            #pragma unroll
            for (int i = 0; i < 4; i++)
                #pragma unroll
                for (int j = 0; j < 8; j++)
                    ffma2(acc2[i][j], a2[i], bd[j]);
        }
        __syncthreads();
        if (more) {
            As[ac0+0][ar0] = na0.x; As[ac0+1][ar0] = na0.y; As[ac0+2][ar0] = na0.z; As[ac0+3][ar0] = na0.w;
            As[ac1+0][ar1] = na1.x; As[ac1+1][ar1] = na1.y; As[ac1+2][ar1] = na1.z; As[ac1+3][ar1] = na1.w;
            Ws[ac0+0][ar0] = nw0.x; Ws[ac0+1][ar0] = nw0.y; Ws[ac0+2][ar0] = nw0.z; Ws[ac0+3][ar0] = nw0.w;
            Ws[ac1+0][ar1] = nw1.x; Ws[ac1+1][ar1] = nw1.y; Ws[ac1+2][ar1] = nw1.z; Ws[ac1+3][ar1] = nw1.w;
        }
        __syncthreads();
    }

    // Epilogue: unpack, add bias, store.
    const int row0 = bm * 128 + tm * 8;
    const int col0 = bn * 128 + tn * 8;
    float bb[8];
    #pragma unroll
    for (int j = 0; j < 8; j++) bb[j] = bias[col0 + j];
    #pragma unroll
    for (int ip = 0; ip < 4; ip++) {
        float r0[8], r1[8];
        #pragma unroll
        for (int j = 0; j < 8; j++) unpack2(r0[j], r1[j], acc2[ip][j]);
        const int r = row0 + 2 * ip;
        *(float4*)&C[(size_t)r * N + col0] =
            make_float4(r0[0] + bb[0], r0[1] + bb[1], r0[2] + bb[2], r0[3] + bb[3]);
        *(float4*)&C[(size_t)r * N + col0 + 4] =
            make_float4(r0[4] + bb[4], r0[5] + bb[5], r0[6] + bb[6], r0[7] + bb[7]);
        *(float4*)&C[(size_t)(r + 1) * N + col0] =
            make_float4(r1[0] + bb[0], r1[1] + bb[1], r1[2] + bb[2], r1[3] + bb[3]);
        *(float4*)&C[(size_t)(r + 1) * N + col0 + 4] =
            make_float4(r1[4] + bb[4], r1[5] + bb[5], r1[6] + bb[6], r1[7] + bb[7]);
    }
}

// ---------------------------------------------------------------------------
// Causal flash attention, fp32 with f32x2 inner products.
// One CTA = (head, 64-query tile). BQ=BK=64, 256 threads, 4x4 micro-tiles.
// ---------------------------------------------------------------------------
#define QP 68
#define FLASH_SMEM ((64 * QP * 3 + 64 * 64 + 3 * 64) * 4)

__global__ void __launch_bounds__(256)
flash_attn()
{
    extern __shared__ float smf[];
    float* Qs  = smf;                 // [d][q], pitch QP, pre-scaled by 1/8
    float* Ks  = Qs + 64 * QP;        // [d][k], pitch QP
    float* Vs  = Ks + 64 * QP;        // [k][v], pitch 64
    float* Ss  = Vs + 64 * 64;        // [k][q], pitch QP
    float* m_s = Ss + 64 * QP;
    float* l_s = m_s + 64;
    float* a_s = l_s + 64;

    const int tid = threadIdx.x;
    const int tm  = tid >> 4;
    const int tn  = tid & 15;
    const int h   = blockIdx.y;
    const int qt  = (int)gridDim.x - 1 - (int)blockIdx.x;
    const int q0  = qt * 64;
    const size_t hoff = (size_t)h * HD;

#pragma unroll
    for (int s = 0; s < 4; s++) {
        int idx = tid + 256 * s;
        int r = idx >> 4;
        int c = (idx & 15) << 2;
        float4 q4 = *(const float4*)&g_Q[(size_t)(q0 + r) * DM + hoff + c];
        Qs[(c + 0) * QP + r] = q4.x * 0.125f;
        Qs[(c + 1) * QP + r] = q4.y * 0.125f;
        Qs[(c + 2) * QP + r] = q4.z * 0.125f;
        Qs[(c + 3) * QP + r] = q4.w * 0.125f;
    }
    if (tid < 64) { m_s[tid] = -1e30f; l_s[tid] = 0.f; }

    // o2[i][vp] = { O[i][2vp], O[i][2vp+1] }
    u64t o2[4][2] = {};

    for (int kt = 0; kt <= qt; kt++) {
        const int k0 = kt * 64;
        __syncthreads();

#pragma unroll
        for (int s = 0; s < 4; s++) {
            int idx = tid + 256 * s;
            int r = idx >> 4;
            int c = (idx & 15) << 2;
            float4 k4 = *(const float4*)&g_K[(size_t)(k0 + r) * DM + hoff + c];
            Ks[(c + 0) * QP + r] = k4.x;
            Ks[(c + 1) * QP + r] = k4.y;
            Ks[(c + 2) * QP + r] = k4.z;
            Ks[(c + 3) * QP + r] = k4.w;
            float4 v4 = *(const float4*)&g_V[(size_t)(k0 + r) * DM + hoff + c];
            *(float4*)&Vs[r * 64 + c] = v4;
        }
        __syncthreads();

        // S = (Q/8) K^T : q-pairs (natural) x dup-k
        u64t s2[2][4] = {};
#pragma unroll 8
        for (int d = 0; d < 64; d++) {
            ulonglong2 qa = *(const ulonglong2*)&Qs[d * QP + (tm << 2)];
            u64t q2[2] = {qa.x, qa.y};
            float4 kb = *(const float4*)&Ks[d * QP + (tn << 2)];
            u64t kd[4] = {packdup(kb.x), packdup(kb.y), packdup(kb.z), packdup(kb.w)};
#pragma unroll
            for (int i = 0; i < 2; i++)
#pragma unroll
                for (int j = 0; j < 4; j++)
                    ffma2(s2[i][j], q2[i], kd[j]);
        }

        float sacc[4][4];
#pragma unroll
        for (int i = 0; i < 2; i++)
#pragma unroll
            for (int j = 0; j < 4; j++)
                unpack2(sacc[2 * i][j], sacc[2 * i + 1][j], s2[i][j]);

        if (kt == qt) {
#pragma unroll
            for (int i = 0; i < 4; i++)
#pragma unroll
                for (int j = 0; j < 4; j++)
                    if ((tn << 2) + j > (tm << 2) + i) sacc[i][j] = -1e30f;
        }

#pragma unroll
        for (int j = 0; j < 4; j++) {
            *(float4*)&Ss[((tn << 2) + j) * QP + (tm << 2)] =
                make_float4(sacc[0][j], sacc[1][j], sacc[2][j], sacc[3][j]);
        }
        __syncthreads();

        if (tid < 64) {
            float mi = m_s[tid];
            float mx = mi;
#pragma unroll 8
            for (int j = 0; j < 64; j++) mx = fmaxf(mx, Ss[j * QP + tid]);
            float alpha = __expf(mi - mx);
            float sum = 0.f;
#pragma unroll 8
            for (int j = 0; j < 64; j++) {
                float p = __expf(Ss[j * QP + tid] - mx);
                Ss[j * QP + tid] = p;
                sum += p;
            }
            m_s[tid] = mx;
            l_s[tid] = l_s[tid] * alpha + sum;
            a_s[tid] = alpha;
        }
        __syncthreads();

        // Rescale running O by alpha (packed), then O += P @ V (p dup x v-pairs)
        {
#pragma unroll
            for (int i = 0; i < 4; i++) {
                u64t ad = packdup(a_s[(tm << 2) + i]);
                fmul2(o2[i][0], o2[i][0], ad);
                fmul2(o2[i][1], o2[i][1], ad);
            }
        }
#pragma unroll 4
        for (int j = 0; j < 64; j++) {
            float4 pa = *(const float4*)&Ss[j * QP + (tm << 2)];
            u64t pd[4] = {packdup(pa.x), packdup(pa.y), packdup(pa.z), packdup(pa.w)};
            ulonglong2 vb = *(const ulonglong2*)&Vs[j * 64 + (tn << 2)];
            u64t v2[2] = {vb.x, vb.y};
#pragma unroll
            for (int i = 0; i < 4; i++)
#pragma unroll
                for (int vp = 0; vp < 2; vp++)
                    ffma2(o2[i][vp], pd[i], v2[vp]);
        }
    }

    // Epilogue: normalize and write
#pragma unroll
    for (int i = 0; i < 4; i++) {
        float inv = 1.f / l_s[(tm << 2) + i];
        float o0, o1, o2v, o3;
        unpack2(o0, o1, o2[i][0]);
        unpack2(o2v, o3, o2[i][1]);
        *(float4*)&g_AO[(size_t)(q0 + (tm << 2) + i) * DM + hoff + (tn << 2)] =
            make_float4(o0 * inv, o1 * inv, o2v * inv, o3 * inv);
    }
}

// ---------------------------------------------------------------------------
extern "C" void kernel_launch(void* const* d_in, const int* in_sizes, int n_in,
                              void* d_out, int out_size)
{
    const float* queries = (const float*)d_in[0];
    const float* keys    = (const float*)d_in[1];
    const float* values  = (const float*)d_in[2];
    const float* Wq      = (const float*)d_in[3];
    const float* bq      = (const float*)d_in[4];
    const float* Wk      = (const float*)d_in[5];
    const float* bk      = (const float*)d_in[6];
    const float* Wv      = (const float*)d_in[7];
    const float* bv      = (const float*)d_in[8];
    const float* Wo      = (const float*)d_in[9];
    const float* bo      = (const float*)d_in[10];
    float* out = (float*)d_out;

    float *Qp, *Kp, *Vp, *AOp;
    cudaGetSymbolAddress((void**)&Qp,  g_Q);
    cudaGetSymbolAddress((void**)&Kp,  g_K);
    cudaGetSymbolAddress((void**)&Vp,  g_V);
    cudaGetSymbolAddress((void**)&AOp, g_AO);

    cudaFuncSetAttribute(flash_attn, cudaFuncAttributeMaxDynamicSharedMemorySize,
                         FLASH_SMEM);

    dim3 ggrid(DM / 128, SEQ / 128);   // (8, 32)

    gemm_bias<<<ggrid, 256>>>(queries, Wq, bq, Qp, SEQ, DM, DM);
    gemm_bias<<<ggrid, 256>>>(keys,    Wk, bk, Kp, SEQ, DM, DM);
    gemm_bias<<<ggrid, 256>>>(values,  Wv, bv, Vp, SEQ, DM, DM);

    flash_attn<<<dim3(SEQ / 64, NH), 256, FLASH_SMEM>>>();

    gemm_bias<<<ggrid, 256>>>(AOp, Wo, bo, out, SEQ, DM, DM);
}

// round 15
// speedup vs baseline: 1.4816x; 1.1498x over previous
#include <cuda_runtime.h>
#include <cstdint>

#define SEQ 4096
#define DM  1024
#define NH  16
#define HD  64

// Scratch (allocation inside kernel_launch is forbidden).
static __device__ float g_Q [SEQ * DM];
static __device__ float g_K [SEQ * DM];
static __device__ float g_V [SEQ * DM];
static __device__ float g_AO[SEQ * DM];

// ---------------------------------------------------------------------------
// Packed fp32x2 helpers (modest win on B300: ~1.33x FMA issue at best)
// ---------------------------------------------------------------------------
typedef unsigned long long u64t;

__device__ __forceinline__ void ffma2(u64t& d, u64t a, u64t b) {
    asm("fma.rn.f32x2 %0, %1, %2, %0;" : "+l"(d) : "l"(a), "l"(b));
}
__device__ __forceinline__ void fmul2(u64t& d, u64t a, u64t b) {
    asm("mul.rn.f32x2 %0, %1, %2;" : "=l"(d) : "l"(a), "l"(b));
}
__device__ __forceinline__ u64t packdup(float x) {
    u64t r;
    asm("mov.b64 %0, {%1, %1};" : "=l"(r) : "f"(x));
    return r;
}
__device__ __forceinline__ void unpack2(float& lo, float& hi, u64t v) {
    asm("mov.b64 {%0, %1}, %2;" : "=f"(lo), "=f"(hi) : "l"(v));
}

// ---------------------------------------------------------------------------
// GEMM core: C[M,N] = A[M,K] @ W[N,K]^T + bias[N]
// 128x128 block tile, K-tile 16, 256 threads, 8x8 micro-tile, f32x2 FMAs.
// ---------------------------------------------------------------------------
__device__ __forceinline__ void gemm_core(
    const float* __restrict__ A, const float* __restrict__ W,
    const float* __restrict__ bias, float* __restrict__ C,
    int M, int N, int K, int bm, int bn)
{
    __shared__ float As[16][132];
    __shared__ float Ws[16][132];

    const int tid = threadIdx.x;
    const int tm  = tid >> 4;
    const int tn  = tid & 15;

    const int i0  = tid * 2;
    const int ar0 = i0 >> 2,       ac0 = (i0 & 3) << 2;
    const int ar1 = (i0 + 1) >> 2, ac1 = ((i0 + 1) & 3) << 2;

    const float* Ab = A + (size_t)bm * 128 * K;
    const float* Wb = W + (size_t)bn * 128 * K;

    u64t acc2[4][8];
    #pragma unroll
    for (int i = 0; i < 4; i++)
        #pragma unroll
        for (int j = 0; j < 8; j++) acc2[i][j] = 0ull;

    const int NK = K >> 4;

    float4 a0 = *(const float4*)(Ab + (size_t)ar0 * K + ac0);
    float4 a1 = *(const float4*)(Ab + (size_t)ar1 * K + ac1);
    float4 w0 = *(const float4*)(Wb + (size_t)ar0 * K + ac0);
    float4 w1 = *(const float4*)(Wb + (size_t)ar1 * K + ac1);
    As[ac0+0][ar0] = a0.x; As[ac0+1][ar0] = a0.y; As[ac0+2][ar0] = a0.z; As[ac0+3][ar0] = a0.w;
    As[ac1+0][ar1] = a1.x; As[ac1+1][ar1] = a1.y; As[ac1+2][ar1] = a1.z; As[ac1+3][ar1] = a1.w;
    Ws[ac0+0][ar0] = w0.x; Ws[ac0+1][ar0] = w0.y; Ws[ac0+2][ar0] = w0.z; Ws[ac0+3][ar0] = w0.w;
    Ws[ac1+0][ar1] = w1.x; Ws[ac1+1][ar1] = w1.y; Ws[ac1+2][ar1] = w1.z; Ws[ac1+3][ar1] = w1.w;
    __syncthreads();

    for (int kt = 0; kt < NK; kt++) {
        const bool more = (kt + 1 < NK);
        float4 na0, na1, nw0, nw1;
        if (more) {
            const float* Ap = Ab + (kt + 1) * 16;
            const float* Wp = Wb + (kt + 1) * 16;
            na0 = *(const float4*)(Ap + (size_t)ar0 * K + ac0);
            na1 = *(const float4*)(Ap + (size_t)ar1 * K + ac1);
            nw0 = *(const float4*)(Wp + (size_t)ar0 * K + ac0);
            nw1 = *(const float4*)(Wp + (size_t)ar1 * K + ac1);
        }

        #pragma unroll
        for (int kk = 0; kk < 16; kk++) {
            ulonglong2 av0 = *(const ulonglong2*)&As[kk][tm * 8];
            ulonglong2 av1 = *(const ulonglong2*)&As[kk][tm * 8 + 4];
            u64t a2[4] = {av0.x, av0.y, av1.x, av1.y};
            float4 bv0 = *(const float4*)&Ws[kk][tn * 8];
            float4 bv1 = *(const float4*)&Ws[kk][tn * 8 + 4];
            u64t bd[8];
            bd[0] = packdup(bv0.x); bd[1] = packdup(bv0.y);
            bd[2] = packdup(bv0.z); bd[3] = packdup(bv0.w);
            bd[4] = packdup(bv1.x); bd[5] = packdup(bv1.y);
            bd[6] = packdup(bv1.z); bd[7] = packdup(bv1.w);
            #pragma unroll
            for (int i = 0; i < 4; i++)
                #pragma unroll
                for (int j = 0; j < 8; j++)
                    ffma2(acc2[i][j], a2[i], bd[j]);
        }
        __syncthreads();
        if (more) {
            As[ac0+0][ar0] = na0.x; As[ac0+1][ar0] = na0.y; As[ac0+2][ar0] = na0.z; As[ac0+3][ar0] = na0.w;
            As[ac1+0][ar1] = na1.x; As[ac1+1][ar1] = na1.y; As[ac1+2][ar1] = na1.z; As[ac1+3][ar1] = na1.w;
            Ws[ac0+0][ar0] = nw0.x; Ws[ac0+1][ar0] = nw0.y; Ws[ac0+2][ar0] = nw0.z; Ws[ac0+3][ar0] = nw0.w;
            Ws[ac1+0][ar1] = nw1.x; Ws[ac1+1][ar1] = nw1.y; Ws[ac1+2][ar1] = nw1.z; Ws[ac1+3][ar1] = nw1.w;
        }
        __syncthreads();
    }

    const int row0 = bm * 128 + tm * 8;
    const int col0 = bn * 128 + tn * 8;
    float bb[8];
    #pragma unroll
    for (int j = 0; j < 8; j++) bb[j] = bias[col0 + j];
    #pragma unroll
    for (int ip = 0; ip < 4; ip++) {
        float r0[8], r1[8];
        #pragma unroll
        for (int j = 0; j < 8; j++) unpack2(r0[j], r1[j], acc2[ip][j]);
        const int r = row0 + 2 * ip;
        *(float4*)&C[(size_t)r * N + col0] =
            make_float4(r0[0] + bb[0], r0[1] + bb[1], r0[2] + bb[2], r0[3] + bb[3]);
        *(float4*)&C[(size_t)r * N + col0 + 4] =
            make_float4(r0[4] + bb[4], r0[5] + bb[5], r0[6] + bb[6], r0[7] + bb[7]);
        *(float4*)&C[(size_t)(r + 1) * N + col0] =
            make_float4(r1[0] + bb[0], r1[1] + bb[1], r1[2] + bb[2], r1[3] + bb[3]);
        *(float4*)&C[(size_t)(r + 1) * N + col0 + 4] =
            make_float4(r1[4] + bb[4], r1[5] + bb[5], r1[6] + bb[6], r1[7] + bb[7]);
    }
}

// Merged QKV projection: blockIdx.z selects (input, weight, bias, output).
__global__ void __launch_bounds__(256, 2)
gemm_qkv(const float* __restrict__ Aq, const float* __restrict__ Ak, const float* __restrict__ Av,
         const float* __restrict__ Wq, const float* __restrict__ Wk, const float* __restrict__ Wv,
         const float* __restrict__ bq, const float* __restrict__ bk, const float* __restrict__ bv,
         float* __restrict__ Cq, float* __restrict__ Ck, float* __restrict__ Cv,
         int M, int N, int K)
{
    const int z = blockIdx.z;
    const float* A = (z == 0) ? Aq : (z == 1) ? Ak : Av;
    const float* W = (z == 0) ? Wq : (z == 1) ? Wk : Wv;
    const float* b = (z == 0) ? bq : (z == 1) ? bk : bv;
    float*       C = (z == 0) ? Cq : (z == 1) ? Ck : Cv;
    gemm_core(A, W, b, C, M, N, K, blockIdx.y, blockIdx.x);
}

__global__ void __launch_bounds__(256, 2)
gemm_bias(const float* __restrict__ A, const float* __restrict__ W,
          const float* __restrict__ bias, float* __restrict__ C,
          int M, int N, int K)
{
    gemm_core(A, W, bias, C, M, N, K, blockIdx.y, blockIdx.x);
}

// ---------------------------------------------------------------------------
// Causal flash attention, fp32. BQ=BK=128, 256 threads.
// Micro-tiles: QK^T 8q x 8k per thread; PV 8q x 4v per thread.
// S stored row-major [q][k] so softmax reads rows and PV reads P by row.
// ---------------------------------------------------------------------------
#define DP 132                      // Qs/Ks pitch ([d][q] / [d][k])
#define SP 132                      // Ss pitch    ([q][k])
#define VPCH 68                     // Vs pitch    ([k][v])
#define FLASH_SMEM ((64*DP*2 + 128*VPCH + 128*SP + 3*128) * 4)   // 171,520 B

__global__ void __launch_bounds__(256, 1)
flash_attn()
{
    extern __shared__ float smf[];
    float* Qs  = smf;                  // [d][q]  64 x DP (pre-scaled by 1/8)
    float* Ks  = Qs + 64 * DP;         // [d][k]  64 x DP
    float* Vs  = Ks + 64 * DP;         // [k][v] 128 x VPCH
    float* Ss  = Vs + 128 * VPCH;      // [q][k] 128 x SP
    float* m_s = Ss + 128 * SP;
    float* l_s = m_s + 128;
    float* a_s = l_s + 128;

    const int tid = threadIdx.x;
    const int tm  = tid >> 4;          // 0..15 -> q rows tm*8..+7
    const int tn  = tid & 15;          // 0..15 -> k cols tn*8..+7 / v cols tn*4..+3
    const int h   = blockIdx.y;
    const int qt  = (int)gridDim.x - 1 - (int)blockIdx.x;  // longest-first
    const int q0  = qt * 128;
    const size_t hoff = (size_t)h * HD;

    // Load Q tile (128 x 64) transposed to [d][q], fused 1/sqrt(64) scale.
#pragma unroll
    for (int s = 0; s < 8; s++) {
        int idx = tid + 256 * s;       // 0..2047
        int r = idx >> 4;              // q row 0..127
        int c = (idx & 15) << 2;       // d col 0..60
        float4 q4 = *(const float4*)&g_Q[(size_t)(q0 + r) * DM + hoff + c];
        Qs[(c + 0) * DP + r] = q4.x * 0.125f;
        Qs[(c + 1) * DP + r] = q4.y * 0.125f;
        Qs[(c + 2) * DP + r] = q4.z * 0.125f;
        Qs[(c + 3) * DP + r] = q4.w * 0.125f;
    }
    if (tid < 128) { m_s[tid] = -1e30f; l_s[tid] = 0.f; }

    // O accumulators: 8 q rows x 4 v cols, packed over v (2 x f32x2 per row).
    u64t o2[8][2] = {};

    for (int kt = 0; kt <= qt; kt++) {
        const int k0 = kt * 128;
        __syncthreads();   // prior tile's PV reads complete before overwrite

        // Load K (transposed [d][k]) and V ([k][v]) tiles.
#pragma unroll
        for (int s = 0; s < 8; s++) {
            int idx = tid + 256 * s;
            int r = idx >> 4;          // k row 0..127
            int c = (idx & 15) << 2;   // d/v col
            float4 k4 = *(const float4*)&g_K[(size_t)(k0 + r) * DM + hoff + c];
            Ks[(c + 0) * DP + r] = k4.x;
            Ks[(c + 1) * DP + r] = k4.y;
            Ks[(c + 2) * DP + r] = k4.z;
            Ks[(c + 3) * DP + r] = k4.w;
            float4 v4 = *(const float4*)&g_V[(size_t)(k0 + r) * DM + hoff + c];
            *(float4*)&Vs[r * VPCH + c] = v4;
        }
        __syncthreads();

        // S = (Q/8) K^T : 8x8 per thread, q-pairs x dup-k.
        u64t s2[4][8];
#pragma unroll
        for (int i = 0; i < 4; i++)
#pragma unroll
            for (int j = 0; j < 8; j++) s2[i][j] = 0ull;

#pragma unroll 8
        for (int d = 0; d < 64; d++) {
            ulonglong2 qa = *(const ulonglong2*)&Qs[d * DP + tm * 8];
            ulonglong2 qb = *(const ulonglong2*)&Qs[d * DP + tm * 8 + 4];
            u64t q2[4] = {qa.x, qa.y, qb.x, qb.y};
            float4 kv0 = *(const float4*)&Ks[d * DP + tn * 8];
            float4 kv1 = *(const float4*)&Ks[d * DP + tn * 8 + 4];
            u64t kd[8];
            kd[0] = packdup(kv0.x); kd[1] = packdup(kv0.y);
            kd[2] = packdup(kv0.z); kd[3] = packdup(kv0.w);
            kd[4] = packdup(kv1.x); kd[5] = packdup(kv1.y);
            kd[6] = packdup(kv1.z); kd[7] = packdup(kv1.w);
#pragma unroll
            for (int i = 0; i < 4; i++)
#pragma unroll
                for (int j = 0; j < 8; j++)
                    ffma2(s2[i][j], q2[i], kd[j]);
        }

        float sacc[8][8];
#pragma unroll
        for (int i = 0; i < 4; i++)
#pragma unroll
            for (int j = 0; j < 8; j++)
                unpack2(sacc[2 * i][j], sacc[2 * i + 1][j], s2[i][j]);

        // Causal mask only on the diagonal tile.
        if (kt == qt) {
#pragma unroll
            for (int i = 0; i < 8; i++)
#pragma unroll
                for (int j = 0; j < 8; j++)
                    if (tn * 8 + j > tm * 8 + i) sacc[i][j] = -1e30f;
        }

        // Store S row-major [q][k].
#pragma unroll
        for (int i = 0; i < 8; i++) {
            *(float4*)&Ss[(tm * 8 + i) * SP + tn * 8] =
                make_float4(sacc[i][0], sacc[i][1], sacc[i][2], sacc[i][3]);
            *(float4*)&Ss[(tm * 8 + i) * SP + tn * 8 + 4] =
                make_float4(sacc[i][4], sacc[i][5], sacc[i][6], sacc[i][7]);
        }
        __syncthreads();

        // Online softmax: thread q handles its contiguous row.
        if (tid < 128) {
            float mi = m_s[tid];
            float mx = mi;
#pragma unroll 8
            for (int kb = 0; kb < 32; kb++) {
                float4 sv = *(const float4*)&Ss[tid * SP + kb * 4];
                mx = fmaxf(mx, fmaxf(fmaxf(sv.x, sv.y), fmaxf(sv.z, sv.w)));
            }
            float alpha = __expf(mi - mx);
            float sum = 0.f;
#pragma unroll 8
            for (int kb = 0; kb < 32; kb++) {
                float4 sv = *(float4*)&Ss[tid * SP + kb * 4];
                sv.x = __expf(sv.x - mx); sv.y = __expf(sv.y - mx);
                sv.z = __expf(sv.z - mx); sv.w = __expf(sv.w - mx);
                *(float4*)&Ss[tid * SP + kb * 4] = sv;
                sum += (sv.x + sv.y) + (sv.z + sv.w);
            }
            m_s[tid] = mx;
            l_s[tid] = l_s[tid] * alpha + sum;
            a_s[tid] = alpha;
        }
        __syncthreads();

        // Rescale running O by alpha.
#pragma unroll
        for (int i = 0; i < 8; i++) {
            u64t ad = packdup(a_s[tm * 8 + i]);
            fmul2(o2[i][0], o2[i][0], ad);
            fmul2(o2[i][1], o2[i][1], ad);
        }

        // O += P @ V : per 4-j block, P rows read as float4, V as v-pairs.
#pragma unroll 4
        for (int jb = 0; jb < 32; jb++) {
            float pr[8][4];
#pragma unroll
            for (int i = 0; i < 8; i++) {
                float4 p4 = *(const float4*)&Ss[(tm * 8 + i) * SP + jb * 4];
                pr[i][0] = p4.x; pr[i][1] = p4.y; pr[i][2] = p4.z; pr[i][3] = p4.w;
            }
#pragma unroll
            for (int jj = 0; jj < 4; jj++) {
                const int j = jb * 4 + jj;
                ulonglong2 vv = *(const ulonglong2*)&Vs[j * VPCH + tn * 4];
#pragma unroll
                for (int i = 0; i < 8; i++) {
                    u64t pd = packdup(pr[i][jj]);
                    ffma2(o2[i][0], pd, vv.x);
                    ffma2(o2[i][1], pd, vv.y);
                }
            }
        }
    }

    // Epilogue: normalize and write [q, h*HD + v].
#pragma unroll
    for (int i = 0; i < 8; i++) {
        float inv = 1.f / l_s[tm * 8 + i];
        float oa, ob, oc, od;
        unpack2(oa, ob, o2[i][0]);
        unpack2(oc, od, o2[i][1]);
        *(float4*)&g_AO[(size_t)(q0 + tm * 8 + i) * DM + hoff + tn * 4] =
            make_float4(oa * inv, ob * inv, oc * inv, od * inv);
    }
}

// ---------------------------------------------------------------------------
extern "C" void kernel_launch(void* const* d_in, const int* in_sizes, int n_in,
                              void* d_out, int out_size)
{
    const float* queries = (const float*)d_in[0];
    const float* keys    = (const float*)d_in[1];
    const float* values  = (const float*)d_in[2];
    const float* Wq      = (const float*)d_in[3];
    const float* bq      = (const float*)d_in[4];
    const float* Wk      = (const float*)d_in[5];
    const float* bk      = (const float*)d_in[6];
    const float* Wv      = (const float*)d_in[7];
    const float* bv      = (const float*)d_in[8];
    const float* Wo      = (const float*)d_in[9];
    const float* bo      = (const float*)d_in[10];
    float* out = (float*)d_out;

    float *Qp, *Kp, *Vp, *AOp;
    cudaGetSymbolAddress((void**)&Qp,  g_Q);
    cudaGetSymbolAddress((void**)&Kp,  g_K);
    cudaGetSymbolAddress((void**)&Vp,  g_V);
    cudaGetSymbolAddress((void**)&AOp, g_AO);

    cudaFuncSetAttribute(flash_attn, cudaFuncAttributeMaxDynamicSharedMemorySize,
                         FLASH_SMEM);

    dim3 qkvgrid(DM / 128, SEQ / 128, 3);   // (8, 32, 3)
    gemm_qkv<<<qkvgrid, 256>>>(queries, keys, values,
                               Wq, Wk, Wv, bq, bk, bv,
                               Qp, Kp, Vp, SEQ, DM, DM);

    flash_attn<<<dim3(SEQ / 128, NH), 256, FLASH_SMEM>>>();

    gemm_bias<<<dim3(DM / 128, SEQ / 128), 256>>>(AOp, Wo, bo, out, SEQ, DM, DM);
}